// round 2
// baseline (speedup 1.0000x reference)
#include <cuda_runtime.h>
#include <math.h>

#define TT   2048
#define DD   1024
#define NH   16
#define HDIM 64
#define WIN  128
#define PSTR 132

// ---------------- scratch (static device globals; no allocation) ----------
__device__ float g_buf[TT * DD];
__device__ float v_buf[TT * DD];
__device__ float o_buf[TT * DD];
__device__ float norm_buf[NH * TT];
__device__ float denom_buf[NH * TT];
__device__ float suminv_buf[NH];
__device__ float p_buf[(size_t)NH * TT * PSTR];

// ---------------- SGEMM: C[MxN] = A[MxK] * B[NxK]^T + bias[N] -------------
#define BM 128
#define BN 128
#define BKK 16
#define TM 8
#define TN 8

__device__ __forceinline__ void sgemm_body(
    const float* __restrict__ A, const float* __restrict__ B,
    const float* __restrict__ bias, float* __restrict__ C,
    int K, int N, int bx, int by)
{
    __shared__ float As[BKK][BM];
    __shared__ float Bs[BKK][BN];

    const int tid = threadIdx.x;          // 256 threads
    const int tx  = tid & 15;
    const int ty  = tid >> 4;
    const int m0  = by * BM;
    const int n0  = bx * BN;

    float acc[TM][TN];
#pragma unroll
    for (int i = 0; i < TM; ++i)
#pragma unroll
        for (int j = 0; j < TN; ++j) acc[i][j] = 0.f;

#pragma unroll 1
    for (int k0 = 0; k0 < K; k0 += BKK) {
#pragma unroll
        for (int l = 0; l < 2; ++l) {
            int li  = tid + l * 256;
            int row = li >> 2;            // 0..127
            int kq  = li & 3;             // 0..3 (float4 along K)
            float4 va = *(const float4*)(A + (size_t)(m0 + row) * K + k0 + kq * 4);
            As[kq * 4 + 0][row] = va.x;
            As[kq * 4 + 1][row] = va.y;
            As[kq * 4 + 2][row] = va.z;
            As[kq * 4 + 3][row] = va.w;
            float4 vb = *(const float4*)(B + (size_t)(n0 + row) * K + k0 + kq * 4);
            Bs[kq * 4 + 0][row] = vb.x;
            Bs[kq * 4 + 1][row] = vb.y;
            Bs[kq * 4 + 2][row] = vb.z;
            Bs[kq * 4 + 3][row] = vb.w;
        }
        __syncthreads();

#pragma unroll
        for (int kk = 0; kk < BKK; ++kk) {
            float ar[TM], br[TN];
            *(float4*)&ar[0] = *(const float4*)&As[kk][ty * TM];
            *(float4*)&ar[4] = *(const float4*)&As[kk][ty * TM + 4];
            *(float4*)&br[0] = *(const float4*)&Bs[kk][tx * TN];
            *(float4*)&br[4] = *(const float4*)&Bs[kk][tx * TN + 4];
#pragma unroll
            for (int i = 0; i < TM; ++i)
#pragma unroll
                for (int j = 0; j < TN; ++j)
                    acc[i][j] = fmaf(ar[i], br[j], acc[i][j]);
        }
        __syncthreads();
    }

    float bb[TN];
#pragma unroll
    for (int j = 0; j < TN; ++j) bb[j] = bias[n0 + tx * TN + j];

#pragma unroll
    for (int i = 0; i < TM; ++i) {
        float* cp = C + (size_t)(m0 + ty * TM + i) * N + n0 + tx * TN;
        float4 o0 = make_float4(acc[i][0] + bb[0], acc[i][1] + bb[1],
                                acc[i][2] + bb[2], acc[i][3] + bb[3]);
        float4 o1 = make_float4(acc[i][4] + bb[4], acc[i][5] + bb[5],
                                acc[i][6] + bb[6], acc[i][7] + bb[7]);
        *(float4*)cp       = o0;
        *(float4*)(cp + 4) = o1;
    }
}

__global__ void __launch_bounds__(256)
k_gv(const float* __restrict__ x,
     const float* __restrict__ Wg, const float* __restrict__ bg,
     const float* __restrict__ Wv, const float* __restrict__ bv)
{
    const float* Bp; const float* bp; float* Cp;
    if (blockIdx.z == 0) { Bp = Wg; bp = bg; Cp = g_buf; }
    else                 { Bp = Wv; bp = bv; Cp = v_buf; }
    sgemm_body(x, Bp, bp, Cp, DD, DD, blockIdx.x, blockIdx.y);
}

__global__ void __launch_bounds__(256)
k_out(const float* __restrict__ Wo, const float* __restrict__ bo,
      float* __restrict__ out)
{
    sgemm_body(o_buf, Wo, bo, out, DD, DD, blockIdx.x, blockIdx.y);
}

// ---------------- per-(h,t) L2 norms of g ---------------------------------
__global__ void __launch_bounds__(256)
k_norm()
{
    const int r    = blockIdx.x * 8 + (threadIdx.x >> 5);  // r = h*TT + t
    const int lane = threadIdx.x & 31;
    const int h    = r >> 11;
    const int t    = r & (TT - 1);
    const float2 v = *(const float2*)(g_buf + (size_t)t * DD + h * HDIM + 2 * lane);
    float s = v.x * v.x + v.y * v.y;
#pragma unroll
    for (int o = 16; o > 0; o >>= 1) s += __shfl_xor_sync(0xffffffffu, s, o);
    if (lane == 0) norm_buf[r] = sqrtf(s);
}

// ---------------- windowed scores + gene_means denom ----------------------
__global__ void __launch_bounds__(128)
k_scores()
{
    const int i   = blockIdx.x;
    const int h   = blockIdx.y;
    const int tid = threadIdx.x;   // 128
    __shared__ float4 gi[16];
    __shared__ float  sred[4];

    if (tid < 16)
        gi[tid] = ((const float4*)(g_buf + (size_t)i * DD + h * HDIM))[tid];
    __syncthreads();

    const int    jstart = (i > WIN) ? (i - WIN) : 0;
    const int    cnt    = i - jstart + 1;          // <= 129
    const float  ni     = norm_buf[h * TT + i];
    const size_t row    = (size_t)(h * TT + i);

    float lsum = 0.f;
    for (int jj = tid; jj < cnt; jj += 128) {
        const int j = jstart + jj;
        const float4* gj = (const float4*)(g_buf + (size_t)j * DD + h * HDIM);
        float dot = 0.f;
#pragma unroll
        for (int q = 0; q < 16; ++q) {
            float4 a = gi[q];
            float4 b = gj[q];
            dot = fmaf(a.x, b.x, dot);
            dot = fmaf(a.y, b.y, dot);
            dot = fmaf(a.z, b.z, dot);
            dot = fmaf(a.w, b.w, dot);
        }
        float c = dot / (ni * norm_buf[h * TT + j] + 1e-8f);
        if (c != c) c = 0.f;                       // nan_to_num
        float p = (c + 1.f) * 0.5f;
        p_buf[row * PSTR + jj] = p;
        lsum += p;
    }

    float s = lsum;
#pragma unroll
    for (int o = 16; o > 0; o >>= 1) s += __shfl_xor_sync(0xffffffffu, s, o);
    if ((tid & 31) == 0) sred[tid >> 5] = s;
    __syncthreads();
    if (tid == 0) {
        float tot = sred[0] + sred[1] + sred[2] + sred[3];
        float gm  = (tot + 0.5f * (float)(TT - cnt)) * (1.f / (float)TT);
        denom_buf[row] = gm + 0.5f;
    }
}

// ---------------- per-head sum of 1/denom ---------------------------------
__global__ void __launch_bounds__(256)
k_suminv()
{
    const int h   = blockIdx.x;
    const int tid = threadIdx.x;   // 256
    __shared__ float sred[8];
    float s = 0.f;
    for (int t = tid; t < TT; t += 256) s += 1.f / denom_buf[h * TT + t];
#pragma unroll
    for (int o = 16; o > 0; o >>= 1) s += __shfl_xor_sync(0xffffffffu, s, o);
    if ((tid & 31) == 0) sred[tid >> 5] = s;
    __syncthreads();
    if (tid == 0) {
        float tot = 0.f;
#pragma unroll
        for (int w = 0; w < 8; ++w) tot += sred[w];
        suminv_buf[h] = tot;
    }
}

// ---------------- softmax over window + attn @ v ---------------------------
__global__ void __launch_bounds__(128)
k_attnv()
{
    const int i   = blockIdx.x;
    const int h   = blockIdx.y;
    const int tid = threadIdx.x;   // 128
    __shared__ float sattn[PSTR];
    __shared__ float sred[4];
    __shared__ float partial[128];

    const int    jstart = (i > WIN) ? (i - WIN) : 0;
    const int    cnt    = i - jstart + 1;
    const size_t row    = (size_t)(h * TT + i);
    const float  fit    = 1.f / (denom_buf[row] * suminv_buf[h]);

    const bool v0 = (tid < cnt);
    const bool v1 = (tid + 128 < cnt);
    float s0 = v0 ? fit * p_buf[row * PSTR + tid]       : -3.4e38f;
    float s1 = v1 ? fit * p_buf[row * PSTR + tid + 128] : -3.4e38f;

    // block max
    float m = fmaxf(s0, s1);
#pragma unroll
    for (int o = 16; o > 0; o >>= 1) m = fmaxf(m, __shfl_xor_sync(0xffffffffu, m, o));
    if ((tid & 31) == 0) sred[tid >> 5] = m;
    __syncthreads();
    m = fmaxf(fmaxf(sred[0], sred[1]), fmaxf(sred[2], sred[3]));
    __syncthreads();

    float e0 = v0 ? __expf(0.f) * expf(s0 - m) : 0.f;
    float e1 = v1 ? expf(s1 - m) : 0.f;
    if (v0) sattn[tid]       = e0;
    if (v1) sattn[tid + 128] = e1;

    // block sum (this sync also publishes sattn)
    float s = e0 + e1;
#pragma unroll
    for (int o = 16; o > 0; o >>= 1) s += __shfl_xor_sync(0xffffffffu, s, o);
    if ((tid & 31) == 0) sred[tid >> 5] = s;
    __syncthreads();
    s = sred[0] + sred[1] + sred[2] + sred[3];
    const float inv = 1.f / s;

    // attn @ v  (2 threads per output dim)
    const int d    = tid & 63;
    const int half = tid >> 6;
    float acc = 0.f;
    for (int jj = half; jj < cnt; jj += 2)
        acc = fmaf(sattn[jj], v_buf[(size_t)(jstart + jj) * DD + h * HDIM + d], acc);
    partial[tid] = acc;
    __syncthreads();
    if (half == 0)
        o_buf[(size_t)i * DD + h * HDIM + d] = (acc + partial[64 + tid]) * inv;
}

// ---------------- launch ---------------------------------------------------
extern "C" void kernel_launch(void* const* d_in, const int* in_sizes, int n_in,
                              void* d_out, int out_size)
{
    const float* x  = (const float*)d_in[0];
    const float* Wg = (const float*)d_in[1];
    const float* bg = (const float*)d_in[2];
    const float* Wv = (const float*)d_in[3];
    const float* bv = (const float*)d_in[4];
    const float* Wo = (const float*)d_in[5];
    const float* bo = (const float*)d_in[6];
    float* out = (float*)d_out;

    dim3 gemm_gv(DD / BN, TT / BM, 2);
    k_gv<<<gemm_gv, 256>>>(x, Wg, bg, Wv, bv);

    k_norm<<<(NH * TT) / 8, 256>>>();

    dim3 attn_grid(TT, NH);
    k_scores<<<attn_grid, 128>>>();
    k_suminv<<<NH, 256>>>();
    k_attnv<<<attn_grid, 128>>>();

    dim3 gemm_o(DD / BN, TT / BM, 1);
    k_out<<<gemm_o, 256>>>(Wo, bo, out);
}

// round 3
// speedup vs baseline: 1.2039x; 1.2039x over previous
#include <cuda_runtime.h>
#include <math.h>

#define TT   2048
#define DD   1024
#define NH   16
#define HDIM 64
#define WIN  128
#define PSTR 132
#define JT   144   // padded window span (max real span = 137)

// ---------------- scratch (static device globals; no allocation) ----------
__device__ float g_buf[TT * DD];
__device__ float v_buf[TT * DD];
__device__ float o_buf[TT * DD];
__device__ float norm_buf[NH * TT];
__device__ float denom_buf[NH * TT];
__device__ float suminv_buf[NH];
__device__ float p_buf[(size_t)NH * TT * PSTR];

// ---------------- packed f32x2 helpers -------------------------------------
__device__ __forceinline__ unsigned long long pack_dup(float a) {
    unsigned long long r;
    unsigned int u = __float_as_uint(a);
    asm("mov.b64 %0, {%1, %1};" : "=l"(r) : "r"(u));
    return r;
}
__device__ __forceinline__ void unpack2(unsigned long long p, float& lo, float& hi) {
    unsigned int ulo, uhi;
    asm("mov.b64 {%0, %1}, %2;" : "=r"(ulo), "=r"(uhi) : "l"(p));
    lo = __uint_as_float(ulo);
    hi = __uint_as_float(uhi);
}
#define FFMA2(acc, a, b) asm("fma.rn.f32x2 %0, %1, %2, %0;" : "+l"(acc) : "l"(a), "l"(b))

// ---------------- SGEMM: C[MxN] = A[MxK] * B[NxK]^T + bias[N] -------------
#define BM 128
#define BN 128
#define BKK 16
#define TM 8
#define TN 8

__device__ __forceinline__ void sgemm_body(
    const float* __restrict__ A, const float* __restrict__ B,
    const float* __restrict__ bias, float* __restrict__ C,
    int K, int N, int bx, int by)
{
    __shared__ __align__(16) float As[BKK][BM];
    __shared__ __align__(16) float Bs[BKK][BN];

    const int tid = threadIdx.x;          // 256 threads
    const int tx  = tid & 15;
    const int ty  = tid >> 4;
    const int m0  = by * BM;
    const int n0  = bx * BN;

    unsigned long long acc[TM][TN / 2];
#pragma unroll
    for (int i = 0; i < TM; ++i)
#pragma unroll
        for (int j = 0; j < TN / 2; ++j) acc[i][j] = 0ull;

#pragma unroll 1
    for (int k0 = 0; k0 < K; k0 += BKK) {
#pragma unroll
        for (int l = 0; l < 2; ++l) {
            int li  = tid + l * 256;
            int row = li >> 2;            // 0..127
            int kq  = li & 3;             // 0..3 (float4 along K)
            float4 va = *(const float4*)(A + (size_t)(m0 + row) * K + k0 + kq * 4);
            As[kq * 4 + 0][row] = va.x;
            As[kq * 4 + 1][row] = va.y;
            As[kq * 4 + 2][row] = va.z;
            As[kq * 4 + 3][row] = va.w;
            float4 vb = *(const float4*)(B + (size_t)(n0 + row) * K + k0 + kq * 4);
            Bs[kq * 4 + 0][row] = vb.x;
            Bs[kq * 4 + 1][row] = vb.y;
            Bs[kq * 4 + 2][row] = vb.z;
            Bs[kq * 4 + 3][row] = vb.w;
        }
        __syncthreads();

#pragma unroll
        for (int kk = 0; kk < BKK; ++kk) {
            float ar[TM];
            *(float4*)&ar[0] = *(const float4*)&As[kk][ty * TM];
            *(float4*)&ar[4] = *(const float4*)&As[kk][ty * TM + 4];
            unsigned long long ad[TM];
#pragma unroll
            for (int i = 0; i < TM; ++i) ad[i] = pack_dup(ar[i]);
            ulonglong2 b0 = *(const ulonglong2*)&Bs[kk][tx * TN];
            ulonglong2 b1 = *(const ulonglong2*)&Bs[kk][tx * TN + 4];
            unsigned long long br[4] = { b0.x, b0.y, b1.x, b1.y };
#pragma unroll
            for (int i = 0; i < TM; ++i)
#pragma unroll
                for (int jp = 0; jp < 4; ++jp)
                    FFMA2(acc[i][jp], ad[i], br[jp]);
        }
        __syncthreads();
    }

    float bb[TN];
#pragma unroll
    for (int j = 0; j < TN; ++j) bb[j] = bias[n0 + tx * TN + j];

#pragma unroll
    for (int i = 0; i < TM; ++i) {
        float o[TN];
#pragma unroll
        for (int jp = 0; jp < 4; ++jp) unpack2(acc[i][jp], o[2 * jp], o[2 * jp + 1]);
        float* cp = C + (size_t)(m0 + ty * TM + i) * N + n0 + tx * TN;
        float4 o0 = make_float4(o[0] + bb[0], o[1] + bb[1], o[2] + bb[2], o[3] + bb[3]);
        float4 o1 = make_float4(o[4] + bb[4], o[5] + bb[5], o[6] + bb[6], o[7] + bb[7]);
        *(float4*)cp       = o0;
        *(float4*)(cp + 4) = o1;
    }
}

__global__ void __launch_bounds__(256)
k_gv(const float* __restrict__ x,
     const float* __restrict__ Wg, const float* __restrict__ bg,
     const float* __restrict__ Wv, const float* __restrict__ bv)
{
    const float* Bp; const float* bp; float* Cp;
    if (blockIdx.z == 0) { Bp = Wg; bp = bg; Cp = g_buf; }
    else                 { Bp = Wv; bp = bv; Cp = v_buf; }
    sgemm_body(x, Bp, bp, Cp, DD, DD, blockIdx.x, blockIdx.y);
}

__global__ void __launch_bounds__(256)
k_out(const float* __restrict__ Wo, const float* __restrict__ bo,
      float* __restrict__ out)
{
    sgemm_body(o_buf, Wo, bo, out, DD, DD, blockIdx.x, blockIdx.y);
}

// ---------------- per-(h,t) L2 norms of g + zero suminv --------------------
__global__ void __launch_bounds__(256)
k_norm()
{
    if (blockIdx.x == 0 && threadIdx.x < NH) suminv_buf[threadIdx.x] = 0.f;
    const int r    = blockIdx.x * 8 + (threadIdx.x >> 5);  // r = h*TT + t
    const int lane = threadIdx.x & 31;
    const int h    = r >> 11;
    const int t    = r & (TT - 1);
    const float2 v = *(const float2*)(g_buf + (size_t)t * DD + h * HDIM + 2 * lane);
    float s = v.x * v.x + v.y * v.y;
#pragma unroll
    for (int o = 16; o > 0; o >>= 1) s += __shfl_xor_sync(0xffffffffu, s, o);
    if (lane == 0) norm_buf[r] = sqrtf(s);
}

// ---------------- windowed scores + gene_means denom (8 rows / block) ------
__global__ void __launch_bounds__(256)
k_scores()
{
    const int i0 = blockIdx.x * 8;
    const int h  = blockIdx.y;
    const int tid = threadIdx.x;

    const int jstart0 = (i0 > WIN) ? (i0 - WIN) : 0;
    const int span    = (i0 + 7) - jstart0 + 1;           // <= 137

    __shared__ __align__(16) float4 gwT[16][JT];   // [q][jj] transposed: conflict-free jj reads
    __shared__ float nw[JT];
    __shared__ float rowsum[8];

    // load window rows of g (head h) into smem, transposed
    const float4* g4 = (const float4*)g_buf;
    for (int idx = tid; idx < span * 16; idx += 256) {
        int jj = idx >> 4;
        int q  = idx & 15;
        gwT[q][jj] = g4[(size_t)(jstart0 + jj) * (DD / 4) + h * (HDIM / 4) + q];
    }
    for (int idx = tid; idx < span; idx += 256)
        nw[idx] = norm_buf[h * TT + jstart0 + idx];
    if (tid < 8) rowsum[tid] = 0.f;
    __syncthreads();

    const int group = tid >> 7;        // 0..1 -> 4 i-rows each
    const int jl    = tid & 127;
    const int ibase = i0 + group * 4;
    const int wi0   = ibase - jstart0;

    float psum[4] = {0.f, 0.f, 0.f, 0.f};

    for (int jj = jl; jj < span; jj += 128) {
        float dot[4] = {0.f, 0.f, 0.f, 0.f};
#pragma unroll
        for (int q = 0; q < 16; ++q) {
            float4 b = gwT[q][jj];
#pragma unroll
            for (int r = 0; r < 4; ++r) {
                float4 a = gwT[q][wi0 + r];
                dot[r] = fmaf(a.x, b.x, dot[r]);
                dot[r] = fmaf(a.y, b.y, dot[r]);
                dot[r] = fmaf(a.z, b.z, dot[r]);
                dot[r] = fmaf(a.w, b.w, dot[r]);
            }
        }
        float njj = nw[jj];
#pragma unroll
        for (int r = 0; r < 4; ++r) {
            const int i   = ibase + r;
            const int wi  = wi0 + r;
            const int off = ((i > WIN) ? (i - WIN) : 0) - jstart0;
            if (jj >= off && jj <= wi) {
                float c = dot[r] / (nw[wi] * njj + 1e-8f);
                if (c != c) c = 0.f;
                float p = (c + 1.f) * 0.5f;
                p_buf[(size_t)(h * TT + i) * PSTR + (jj - off)] = p;
                psum[r] += p;
            }
        }
    }

    // warp-reduce partial sums, accumulate into shared rowsum
#pragma unroll
    for (int r = 0; r < 4; ++r) {
        float s = psum[r];
#pragma unroll
        for (int o = 16; o > 0; o >>= 1) s += __shfl_xor_sync(0xffffffffu, s, o);
        if ((tid & 31) == 0) atomicAdd(&rowsum[group * 4 + r], s);
    }
    __syncthreads();

    if (tid < 8) {
        const int i   = i0 + tid;
        const int cnt = i - ((i > WIN) ? (i - WIN) : 0) + 1;
        float gm = (rowsum[tid] + 0.5f * (float)(TT - cnt)) * (1.f / (float)TT);
        float dn = gm + 0.5f;
        denom_buf[h * TT + i] = dn;
        atomicAdd(&suminv_buf[h], 1.f / dn);
    }
}

// ---------------- softmax over window + attn @ v (8 rows / block) ----------
__global__ void __launch_bounds__(256)
k_attnv()
{
    const int i0 = blockIdx.x * 8;
    const int h  = blockIdx.y;
    const int tid = threadIdx.x;
    const int wid = tid >> 5;
    const int lane = tid & 31;

    const int jstart0 = (i0 > WIN) ? (i0 - WIN) : 0;
    const int span    = (i0 + 7) - jstart0 + 1;           // <= 137

    __shared__ __align__(16) float vw[JT][HDIM];   // natural layout: lane-d reads conflict-free
    __shared__ float sattn[8][JT];
    __shared__ float invs[8];
    __shared__ float red[4][8][HDIM];

    // load window rows of v (head h) into smem
    const float4* v4 = (const float4*)v_buf;
    for (int idx = tid; idx < span * 16; idx += 256) {
        int jj = idx >> 4;
        int q  = idx & 15;
        ((float4*)&vw[jj][0])[q] = v4[(size_t)(jstart0 + jj) * (DD / 4) + h * (HDIM / 4) + q];
    }
    __syncthreads();

    // phase A: warp w -> softmax for row i0+w
    {
        const int i   = i0 + wid;
        const size_t row = (size_t)h * TT + i;
        const float fit  = 1.f / (denom_buf[row] * suminv_buf[h]);
        const int off = ((i > WIN) ? (i - WIN) : 0) - jstart0;
        const int wi  = i - jstart0;

        float m = -1e30f;
        for (int q = lane; q < JT; q += 32) {
            bool in = (q >= off) && (q <= wi);
            float s = in ? fit * p_buf[row * PSTR + (q - off)] : -1e30f;
            sattn[wid][q] = s;
            m = fmaxf(m, s);
        }
#pragma unroll
        for (int o = 16; o > 0; o >>= 1) m = fmaxf(m, __shfl_xor_sync(0xffffffffu, m, o));

        float ss = 0.f;
        for (int q = lane; q < JT; q += 32) {
            float e = expf(sattn[wid][q] - m);    // padding: exp(-huge) == 0
            sattn[wid][q] = e;
            ss += e;
        }
#pragma unroll
        for (int o = 16; o > 0; o >>= 1) ss += __shfl_xor_sync(0xffffffffu, ss, o);
        if (lane == 0) invs[wid] = 1.f / ss;
    }
    __syncthreads();

    // phase B: attn @ v.  thread = (d, quarter)
    {
        const int d  = tid & 63;
        const int qq = tid >> 6;
        float acc[8] = {0.f, 0.f, 0.f, 0.f, 0.f, 0.f, 0.f, 0.f};
        for (int jj = qq; jj < span; jj += 4) {
            float vv = vw[jj][d];
#pragma unroll
            for (int w = 0; w < 8; ++w)
                acc[w] = fmaf(sattn[w][jj], vv, acc[w]);
        }
#pragma unroll
        for (int w = 0; w < 8; ++w) red[qq][w][d] = acc[w];
        __syncthreads();
        if (qq == 0) {
#pragma unroll
            for (int w = 0; w < 8; ++w) {
                float s = red[0][w][d] + red[1][w][d] + red[2][w][d] + red[3][w][d];
                o_buf[(size_t)(i0 + w) * DD + h * HDIM + d] = s * invs[w];
            }
        }
    }
}

// ---------------- launch ---------------------------------------------------
extern "C" void kernel_launch(void* const* d_in, const int* in_sizes, int n_in,
                              void* d_out, int out_size)
{
    const float* x  = (const float*)d_in[0];
    const float* Wg = (const float*)d_in[1];
    const float* bg = (const float*)d_in[2];
    const float* Wv = (const float*)d_in[3];
    const float* bv = (const float*)d_in[4];
    const float* Wo = (const float*)d_in[5];
    const float* bo = (const float*)d_in[6];
    float* out = (float*)d_out;

    dim3 gemm_gv(DD / BN, TT / BM, 2);
    k_gv<<<gemm_gv, 256>>>(x, Wg, bg, Wv, bv);

    k_norm<<<(NH * TT) / 8, 256>>>();

    dim3 attn_grid(TT / 8, NH);
    k_scores<<<attn_grid, 256>>>();
    k_attnv<<<attn_grid, 256>>>();

    dim3 gemm_o(DD / BN, TT / BM, 1);
    k_out<<<gemm_o, 256>>>(Wo, bo, out);
}

// round 5
// speedup vs baseline: 2.0538x; 1.7060x over previous
#include <cuda_runtime.h>
#include <cuda_bf16.h>
#include <math.h>
#include <stdint.h>

#define TT   2048
#define DD   1024
#define NH   16
#define HDIM 64
#define WIN  128
#define PSTR 132
#define JT   144

// ---------------- scratch (static device globals; no allocation) ----------
__device__ float g_buf[TT * DD];
__device__ float v_buf[TT * DD];
__device__ float o_buf[TT * DD];
__device__ float norm_buf[NH * TT];
__device__ float denom_buf[NH * TT];
__device__ float suminv_buf[NH];
__device__ float p_buf[(size_t)NH * TT * PSTR];

// bf16 hi/lo split buffers
__device__ __nv_bfloat16 xh_buf[TT * DD], xl_buf[TT * DD];
__device__ __nv_bfloat16 oh_buf[TT * DD], ol_buf[TT * DD];
__device__ __nv_bfloat16 wgh_buf[DD * DD], wgl_buf[DD * DD];
__device__ __nv_bfloat16 wvh_buf[DD * DD], wvl_buf[DD * DD];
__device__ __nv_bfloat16 woh_buf[DD * DD], wol_buf[DD * DD];

// ---------------- PTX helpers ----------------------------------------------
__device__ __forceinline__ uint32_t s2u(const void* p) {
    uint32_t a;
    asm("{ .reg .u64 t; cvta.to.shared.u64 t, %1; cvt.u32.u64 %0, t; }"
        : "=r"(a) : "l"(p));
    return a;
}
#define CP_ASYNC16(dst, src) \
    asm volatile("cp.async.cg.shared.global [%0], [%1], 16;" :: "r"(dst), "l"(src))
#define CP_COMMIT()  asm volatile("cp.async.commit_group;" ::: "memory")
#define CP_WAIT1()   asm volatile("cp.async.wait_group 1;" ::: "memory")
#define CP_WAIT0()   asm volatile("cp.async.wait_group 0;" ::: "memory")

__device__ __forceinline__ void ldsm_x4(uint32_t& r0, uint32_t& r1,
                                        uint32_t& r2, uint32_t& r3, uint32_t a) {
    asm volatile("ldmatrix.sync.aligned.m8n8.x4.shared.b16 {%0,%1,%2,%3}, [%4];"
                 : "=r"(r0), "=r"(r1), "=r"(r2), "=r"(r3) : "r"(a));
}
__device__ __forceinline__ void mma16816(float* d, const uint32_t* a, const uint32_t* b) {
    asm volatile(
        "mma.sync.aligned.m16n8k16.row.col.f32.bf16.bf16.f32 "
        "{%0,%1,%2,%3}, {%4,%5,%6,%7}, {%8,%9}, {%0,%1,%2,%3};"
        : "+f"(d[0]), "+f"(d[1]), "+f"(d[2]), "+f"(d[3])
        : "r"(a[0]), "r"(a[1]), "r"(a[2]), "r"(a[3]), "r"(b[0]), "r"(b[1]));
}
__device__ __forceinline__ uint32_t sw128(uint32_t off) {
    return off ^ ((off >> 3) & 0x70u);
}

// ---------------- fp32->bf16 hi/lo split conversion -------------------------
// which: 0=x, 1=Wg, 2=Wv, 3=Wo, 4=o_buf
__global__ void __launch_bounds__(256)
k_conv(const float* __restrict__ src, int which)
{
    __nv_bfloat16 *dh, *dl;
    switch (which) {
        case 0:  dh = xh_buf;  dl = xl_buf;  break;
        case 1:  dh = wgh_buf; dl = wgl_buf; break;
        case 2:  dh = wvh_buf; dl = wvl_buf; break;
        case 3:  dh = woh_buf; dl = wol_buf; break;
        default: dh = oh_buf;  dl = ol_buf;  src = o_buf; break;
    }
    const int i = blockIdx.x * 256 + threadIdx.x;
    float4 v = ((const float4*)src)[i];
    __nv_bfloat16 h0 = __float2bfloat16(v.x), h1 = __float2bfloat16(v.y),
                  h2 = __float2bfloat16(v.z), h3 = __float2bfloat16(v.w);
    __nv_bfloat16 l0 = __float2bfloat16(v.x - __bfloat162float(h0)),
                  l1 = __float2bfloat16(v.y - __bfloat162float(h1)),
                  l2 = __float2bfloat16(v.z - __bfloat162float(h2)),
                  l3 = __float2bfloat16(v.w - __bfloat162float(h3));
    __nv_bfloat162 hp0(h0, h1), hp1(h2, h3), lp0(l0, l1), lp1(l2, l3);
    uint2 uh, ul;
    uh.x = *(unsigned*)&hp0; uh.y = *(unsigned*)&hp1;
    ul.x = *(unsigned*)&lp0; ul.y = *(unsigned*)&lp1;
    ((uint2*)dh)[i] = uh;
    ((uint2*)dl)[i] = ul;
}

// ---------------- HMMA bf16-split GEMM --------------------------------------
// C[128x128] = (Ah+Al)[M,K]*(Bh+Bl)[N,K]^T + bias  (drop Al*Bl)
#define KC     64
#define NCHUNK (DD / KC)            // 16
#define TSZ    16384                // 128 rows x 128 B
#define STGSZ  (4 * TSZ)            // Ah, Al, Bh, Bl
#define SMEM_DYN (2 * STGSZ)        // 128 KB

__device__ __forceinline__ void load_stage(
    const uint4* __restrict__ Ah4, const uint4* __restrict__ Al4,
    const uint4* __restrict__ Bh4, const uint4* __restrict__ Bl4,
    uint32_t sb, int s, int c, int m0, int n0, int tid)
{
    const uint32_t stage = sb + s * STGSZ;
#pragma unroll
    for (int t = 0; t < 16; ++t) {
        const int idx  = t * 256 + tid;        // 0..4095
        const int tile = idx >> 10;            // 0..3
        const int row  = (idx >> 3) & 127;
        const int q    = idx & 7;
        const uint32_t dst = stage + tile * TSZ + sw128((uint32_t)row * 128u + q * 16u);
        const size_t ga = (size_t)(m0 + row) * (DD / 8) + c * 8 + q;
        const size_t gb = (size_t)(n0 + row) * (DD / 8) + c * 8 + q;
        const uint4* src;
        if      (tile == 0) src = Ah4 + ga;
        else if (tile == 1) src = Al4 + ga;
        else if (tile == 2) src = Bh4 + gb;
        else                src = Bl4 + gb;
        CP_ASYNC16(dst, src);
    }
}

__device__ __forceinline__ void gemm_core(
    const uint4* __restrict__ Ah4, const uint4* __restrict__ Al4,
    const uint4* __restrict__ Bh4, const uint4* __restrict__ Bl4,
    const float* __restrict__ bias, float* __restrict__ C)
{
    extern __shared__ char smem[];
    const uint32_t sb = s2u(smem);
    const int tid  = threadIdx.x;
    const int wid  = tid >> 5;
    const int lane = tid & 31;
    const int n0 = blockIdx.x * 128, m0 = blockIdx.y * 128;

    const int warp_m = (wid >> 1) * 32;     // 0,32,64,96
    const int warp_n = (wid & 1) * 64;      // 0,64

    // per-lane ldmatrix addressing constants
    const int r  = lane & 7;
    const int md = lane >> 3;
    const int rowA = warp_m + (md & 1) * 8 + r;     // + f*16
    const int bA   = (md >> 1) * 16;                // + ks*32
    const int rowB = warp_n + (md >> 1) * 8 + r;    // + p*16
    const int bB   = (md & 1) * 16;                 // + ks*32

    float acc[2][8][4];
#pragma unroll
    for (int f = 0; f < 2; ++f)
#pragma unroll
        for (int j = 0; j < 8; ++j)
#pragma unroll
            for (int e = 0; e < 4; ++e) acc[f][j][e] = 0.f;

    load_stage(Ah4, Al4, Bh4, Bl4, sb, 0, 0, m0, n0, tid); CP_COMMIT();
    load_stage(Ah4, Al4, Bh4, Bl4, sb, 1, 1, m0, n0, tid); CP_COMMIT();

#pragma unroll 1
    for (int c = 0; c < NCHUNK; ++c) {
        if (c + 2 < NCHUNK) CP_WAIT1(); else CP_WAIT0();
        __syncthreads();

        const int s = c & 1;
        const uint32_t stA = sb + s * STGSZ;
        const uint32_t stB = stA + 2 * TSZ;

#pragma unroll
        for (int ks = 0; ks < 4; ++ks) {
            const uint32_t kb = ks * 32;
            uint32_t ah[2][4], al[2][4];
#pragma unroll
            for (int f = 0; f < 2; ++f) {
                const uint32_t off = sw128((uint32_t)(rowA + f * 16) * 128u + kb + bA);
                ldsm_x4(ah[f][0], ah[f][1], ah[f][2], ah[f][3], stA + off);
                ldsm_x4(al[f][0], al[f][1], al[f][2], al[f][3], stA + TSZ + off);
            }
            uint32_t bh[8][2], bl[8][2];
#pragma unroll
            for (int p = 0; p < 4; ++p) {
                const uint32_t off = sw128((uint32_t)(rowB + p * 16) * 128u + kb + bB);
                ldsm_x4(bh[2*p][0], bh[2*p][1], bh[2*p+1][0], bh[2*p+1][1], stB + off);
                ldsm_x4(bl[2*p][0], bl[2*p][1], bl[2*p+1][0], bl[2*p+1][1], stB + TSZ + off);
            }
#pragma unroll
            for (int f = 0; f < 2; ++f)
#pragma unroll
                for (int j = 0; j < 8; ++j) {
                    mma16816(acc[f][j], ah[f], bh[j]);
                    mma16816(acc[f][j], ah[f], bl[j]);
                    mma16816(acc[f][j], al[f], bh[j]);
                }
        }
        __syncthreads();
        if (c + 2 < NCHUNK) {
            load_stage(Ah4, Al4, Bh4, Bl4, sb, s, c + 2, m0, n0, tid);
            CP_COMMIT();
        }
    }

    // epilogue
    const int colb = warp_n + (lane & 3) * 2;
#pragma unroll
    for (int f = 0; f < 2; ++f) {
        const int grow = m0 + warp_m + f * 16 + (lane >> 2);
        float* c0 = C + (size_t)grow * DD + n0 + colb;
        float* c1 = c0 + 8 * DD;
#pragma unroll
        for (int j = 0; j < 8; ++j) {
            const float2 bb = *(const float2*)(bias + n0 + colb + j * 8);
            float2 o0 = make_float2(acc[f][j][0] + bb.x, acc[f][j][1] + bb.y);
            float2 o1 = make_float2(acc[f][j][2] + bb.x, acc[f][j][3] + bb.y);
            *(float2*)(c0 + j * 8) = o0;
            *(float2*)(c1 + j * 8) = o1;
        }
    }
}

__global__ void __launch_bounds__(256, 1)
k_gemm_gv(const float* __restrict__ bg, const float* __restrict__ bv)
{
    if (blockIdx.z == 0)
        gemm_core((const uint4*)xh_buf, (const uint4*)xl_buf,
                  (const uint4*)wgh_buf, (const uint4*)wgl_buf, bg, g_buf);
    else
        gemm_core((const uint4*)xh_buf, (const uint4*)xl_buf,
                  (const uint4*)wvh_buf, (const uint4*)wvl_buf, bv, v_buf);
}

__global__ void __launch_bounds__(256, 1)
k_gemm_o(const float* __restrict__ bo, float* __restrict__ out)
{
    gemm_core((const uint4*)oh_buf, (const uint4*)ol_buf,
              (const uint4*)woh_buf, (const uint4*)wol_buf, bo, out);
}

// ---------------- per-(h,t) L2 norms of g + zero suminv --------------------
__global__ void __launch_bounds__(256)
k_norm()
{
    if (blockIdx.x == 0 && threadIdx.x < NH) suminv_buf[threadIdx.x] = 0.f;
    const int r    = blockIdx.x * 8 + (threadIdx.x >> 5);
    const int lane = threadIdx.x & 31;
    const int h    = r >> 11;
    const int t    = r & (TT - 1);
    const float2 v = *(const float2*)(g_buf + (size_t)t * DD + h * HDIM + 2 * lane);
    float s = v.x * v.x + v.y * v.y;
#pragma unroll
    for (int o = 16; o > 0; o >>= 1) s += __shfl_xor_sync(0xffffffffu, s, o);
    if (lane == 0) norm_buf[r] = sqrtf(s);
}

// ---------------- windowed scores + gene_means denom (8 rows / block) ------
__global__ void __launch_bounds__(256)
k_scores()
{
    const int i0 = blockIdx.x * 8;
    const int h  = blockIdx.y;
    const int tid = threadIdx.x;

    const int jstart0 = (i0 > WIN) ? (i0 - WIN) : 0;
    const int span    = (i0 + 7) - jstart0 + 1;

    __shared__ __align__(16) float4 gwT[16][JT];
    __shared__ float nw[JT];
    __shared__ float rowsum[8];

    const float4* g4 = (const float4*)g_buf;
    for (int idx = tid; idx < span * 16; idx += 256) {
        int jj = idx >> 4;
        int q  = idx & 15;
        gwT[q][jj] = g4[(size_t)(jstart0 + jj) * (DD / 4) + h * (HDIM / 4) + q];
    }
    for (int idx = tid; idx < span; idx += 256)
        nw[idx] = norm_buf[h * TT + jstart0 + idx];
    if (tid < 8) rowsum[tid] = 0.f;
    __syncthreads();

    const int group = tid >> 7;
    const int jl    = tid & 127;
    const int ibase = i0 + group * 4;
    const int wi0   = ibase - jstart0;

    float psum[4] = {0.f, 0.f, 0.f, 0.f};

    for (int jj = jl; jj < span; jj += 128) {
        float dot[4] = {0.f, 0.f, 0.f, 0.f};
#pragma unroll
        for (int q = 0; q < 16; ++q) {
            float4 b = gwT[q][jj];
#pragma unroll
            for (int r = 0; r < 4; ++r) {
                float4 a = gwT[q][wi0 + r];
                dot[r] = fmaf(a.x, b.x, dot[r]);
                dot[r] = fmaf(a.y, b.y, dot[r]);
                dot[r] = fmaf(a.z, b.z, dot[r]);
                dot[r] = fmaf(a.w, b.w, dot[r]);
            }
        }
        float njj = nw[jj];
#pragma unroll
        for (int r = 0; r < 4; ++r) {
            const int i   = ibase + r;
            const int wi  = wi0 + r;
            const int off = ((i > WIN) ? (i - WIN) : 0) - jstart0;
            if (jj >= off && jj <= wi) {
                float c = dot[r] / (nw[wi] * njj + 1e-8f);
                if (c != c) c = 0.f;
                float p = (c + 1.f) * 0.5f;
                p_buf[(size_t)(h * TT + i) * PSTR + (jj - off)] = p;
                psum[r] += p;
            }
        }
    }

#pragma unroll
    for (int r = 0; r < 4; ++r) {
        float s = psum[r];
#pragma unroll
        for (int o = 16; o > 0; o >>= 1) s += __shfl_xor_sync(0xffffffffu, s, o);
        if ((tid & 31) == 0) atomicAdd(&rowsum[group * 4 + r], s);
    }
    __syncthreads();

    if (tid < 8) {
        const int i   = i0 + tid;
        const int cnt = i - ((i > WIN) ? (i - WIN) : 0) + 1;
        float gm = (rowsum[tid] + 0.5f * (float)(TT - cnt)) * (1.f / (float)TT);
        float dn = gm + 0.5f;
        denom_buf[h * TT + i] = dn;
        atomicAdd(&suminv_buf[h], 1.f / dn);
    }
}

// ---------------- softmax over window + attn @ v (8 rows / block) ----------
__global__ void __launch_bounds__(256)
k_attnv()
{
    const int i0 = blockIdx.x * 8;
    const int h  = blockIdx.y;
    const int tid = threadIdx.x;
    const int wid = tid >> 5;
    const int lane = tid & 31;

    const int jstart0 = (i0 > WIN) ? (i0 - WIN) : 0;
    const int span    = (i0 + 7) - jstart0 + 1;

    __shared__ __align__(16) float vw[JT][HDIM];
    __shared__ float sattn[8][JT];
    __shared__ float invs[8];
    __shared__ float red[4][8][HDIM];

    const float4* v4 = (const float4*)v_buf;
    for (int idx = tid; idx < span * 16; idx += 256) {
        int jj = idx >> 4;
        int q  = idx & 15;
        ((float4*)&vw[jj][0])[q] = v4[(size_t)(jstart0 + jj) * (DD / 4) + h * (HDIM / 4) + q];
    }
    __syncthreads();

    {
        const int i   = i0 + wid;
        const size_t row = (size_t)h * TT + i;
        const float fit  = 1.f / (denom_buf[row] * suminv_buf[h]);
        const int off = ((i > WIN) ? (i - WIN) : 0) - jstart0;
        const int wi  = i - jstart0;

        float m = -1e30f;
        for (int q = lane; q < JT; q += 32) {
            bool in = (q >= off) && (q <= wi);
            float s = in ? fit * p_buf[row * PSTR + (q - off)] : -1e30f;
            sattn[wid][q] = s;
            m = fmaxf(m, s);
        }
#pragma unroll
        for (int o = 16; o > 0; o >>= 1) m = fmaxf(m, __shfl_xor_sync(0xffffffffu, m, o));

        float ss = 0.f;
        for (int q = lane; q < JT; q += 32) {
            float e = expf(sattn[wid][q] - m);
            sattn[wid][q] = e;
            ss += e;
        }
#pragma unroll
        for (int o = 16; o > 0; o >>= 1) ss += __shfl_xor_sync(0xffffffffu, ss, o);
        if (lane == 0) invs[wid] = 1.f / ss;
    }
    __syncthreads();

    {
        const int d  = tid & 63;
        const int qq = tid >> 6;
        float acc[8] = {0.f, 0.f, 0.f, 0.f, 0.f, 0.f, 0.f, 0.f};
        for (int jj = qq; jj < span; jj += 4) {
            float vv = vw[jj][d];
#pragma unroll
            for (int w = 0; w < 8; ++w)
                acc[w] = fmaf(sattn[w][jj], vv, acc[w]);
        }
#pragma unroll
        for (int w = 0; w < 8; ++w) red[qq][w][d] = acc[w];
        __syncthreads();
        if (qq == 0) {
#pragma unroll
            for (int w = 0; w < 8; ++w) {
                float s = red[0][w][d] + red[1][w][d] + red[2][w][d] + red[3][w][d];
                o_buf[(size_t)(i0 + w) * DD + h * HDIM + d] = s * invs[w];
            }
        }
    }
}

// ---------------- launch ---------------------------------------------------
extern "C" void kernel_launch(void* const* d_in, const int* in_sizes, int n_in,
                              void* d_out, int out_size)
{
    const float* x  = (const float*)d_in[0];
    const float* Wg = (const float*)d_in[1];
    const float* bg = (const float*)d_in[2];
    const float* Wv = (const float*)d_in[3];
    const float* bv = (const float*)d_in[4];
    const float* Wo = (const float*)d_in[5];
    const float* bo = (const float*)d_in[6];
    float* out = (float*)d_out;

    cudaFuncSetAttribute(k_gemm_gv, cudaFuncAttributeMaxDynamicSharedMemorySize, SMEM_DYN);
    cudaFuncSetAttribute(k_gemm_o,  cudaFuncAttributeMaxDynamicSharedMemorySize, SMEM_DYN);

    k_conv<<<(TT * DD) / 1024, 256>>>(x,  0);
    k_conv<<<(DD * DD) / 1024, 256>>>(Wg, 1);
    k_conv<<<(DD * DD) / 1024, 256>>>(Wv, 2);
    k_conv<<<(DD * DD) / 1024, 256>>>(Wo, 3);

    dim3 gemm_gv(DD / 128, TT / 128, 2);
    k_gemm_gv<<<gemm_gv, 256, SMEM_DYN>>>(bg, bv);

    k_norm<<<(NH * TT) / 8, 256>>>();

    dim3 attn_grid(TT / 8, NH);
    k_scores<<<attn_grid, 256>>>();
    k_attnv<<<attn_grid, 256>>>();

    k_conv<<<(TT * DD) / 1024, 256>>>(nullptr, 4);
    dim3 gemm_o(DD / 128, TT / 128, 1);
    k_gemm_o<<<gemm_o, 256, SMEM_DYN>>>(bo, out);
}

// round 6
// speedup vs baseline: 2.1114x; 1.0281x over previous
#include <cuda_runtime.h>
#include <cuda_bf16.h>
#include <math.h>
#include <stdint.h>

#define TT   2048
#define DD   1024
#define NH   16
#define HDIM 64
#define WIN  128
#define PSTR 132
#define JT   144
#define IT   16
#define JTA  148

// ---------------- scratch (static device globals; no allocation) ----------
__device__ float g_buf[TT * DD];
__device__ float v_buf[TT * DD];
__device__ float norm_buf[NH * TT];
__device__ float denom_buf[NH * TT];
__device__ float suminv_buf[NH];
__device__ float p_buf[(size_t)NH * TT * PSTR];

__device__ __nv_bfloat16 xh_buf[TT * DD], xl_buf[TT * DD];
__device__ __nv_bfloat16 oh_buf[TT * DD], ol_buf[TT * DD];
__device__ __nv_bfloat16 wgh_buf[DD * DD], wgl_buf[DD * DD];
__device__ __nv_bfloat16 wvh_buf[DD * DD], wvl_buf[DD * DD];
__device__ __nv_bfloat16 woh_buf[DD * DD], wol_buf[DD * DD];

// ---------------- PTX helpers ----------------------------------------------
__device__ __forceinline__ uint32_t s2u(const void* p) {
    uint32_t a;
    asm("{ .reg .u64 t; cvta.to.shared.u64 t, %1; cvt.u32.u64 %0, t; }"
        : "=r"(a) : "l"(p));
    return a;
}
#define CP_ASYNC16(dst, src) \
    asm volatile("cp.async.cg.shared.global [%0], [%1], 16;" :: "r"(dst), "l"(src))
#define CP_COMMIT()  asm volatile("cp.async.commit_group;" ::: "memory")
#define CP_WAIT2()   asm volatile("cp.async.wait_group 2;" ::: "memory")
#define CP_WAIT1()   asm volatile("cp.async.wait_group 1;" ::: "memory")
#define CP_WAIT0()   asm volatile("cp.async.wait_group 0;" ::: "memory")

__device__ __forceinline__ void ldsm_x4(uint32_t& r0, uint32_t& r1,
                                        uint32_t& r2, uint32_t& r3, uint32_t a) {
    asm volatile("ldmatrix.sync.aligned.m8n8.x4.shared.b16 {%0,%1,%2,%3}, [%4];"
                 : "=r"(r0), "=r"(r1), "=r"(r2), "=r"(r3) : "r"(a));
}
__device__ __forceinline__ void mma16816(float* d, const uint32_t* a, const uint32_t* b) {
    asm volatile(
        "mma.sync.aligned.m16n8k16.row.col.f32.bf16.bf16.f32 "
        "{%0,%1,%2,%3}, {%4,%5,%6,%7}, {%8,%9}, {%0,%1,%2,%3};"
        : "+f"(d[0]), "+f"(d[1]), "+f"(d[2]), "+f"(d[3])
        : "r"(a[0]), "r"(a[1]), "r"(a[2]), "r"(a[3]), "r"(b[0]), "r"(b[1]));
}
__device__ __forceinline__ uint32_t sw64(uint32_t off) {
    return off ^ ((off >> 3) & 0x30u);
}

// ---------------- fp32->bf16 hi/lo split conversion -------------------------
__global__ void __launch_bounds__(256)
k_conv(const float* __restrict__ src, int which)
{
    __nv_bfloat16 *dh, *dl;
    switch (which) {
        case 0:  dh = xh_buf;  dl = xl_buf;  break;
        case 1:  dh = wgh_buf; dl = wgl_buf; break;
        case 2:  dh = wvh_buf; dl = wvl_buf; break;
        default: dh = woh_buf; dl = wol_buf; break;
    }
    const int i = blockIdx.x * 256 + threadIdx.x;
    float4 v = ((const float4*)src)[i];
    __nv_bfloat16 h0 = __float2bfloat16(v.x), h1 = __float2bfloat16(v.y),
                  h2 = __float2bfloat16(v.z), h3 = __float2bfloat16(v.w);
    __nv_bfloat16 l0 = __float2bfloat16(v.x - __bfloat162float(h0)),
                  l1 = __float2bfloat16(v.y - __bfloat162float(h1)),
                  l2 = __float2bfloat16(v.z - __bfloat162float(h2)),
                  l3 = __float2bfloat16(v.w - __bfloat162float(h3));
    __nv_bfloat162 hp0(h0, h1), hp1(h2, h3), lp0(l0, l1), lp1(l2, l3);
    uint2 uh, ul;
    uh.x = *(unsigned*)&hp0; uh.y = *(unsigned*)&hp1;
    ul.x = *(unsigned*)&lp0; ul.y = *(unsigned*)&lp1;
    ((uint2*)dh)[i] = uh;
    ((uint2*)dl)[i] = ul;
}

// ---------------- HMMA bf16-split GEMM --------------------------------------
// CTA tile 128x64, warp tile 32x32 (4x2 warps), K-chunk 32, 4-stage cp.async.
#define KC32   32
#define NC     (DD / KC32)          // 32 chunks
#define ATSZ   8192                 // 128 rows x 64B
#define BTSZ   4096                 // 64 rows x 64B
#define STG    (2 * ATSZ + 2 * BTSZ)   // 24576
#define NSTAGE 4
#define SMEM_G (NSTAGE * STG)       // 98304

__device__ __forceinline__ void load_stage(
    const uint4* __restrict__ Ah4, const uint4* __restrict__ Al4,
    const uint4* __restrict__ Bh4, const uint4* __restrict__ Bl4,
    uint32_t sb, int slot, int c, int m0, int n0, int tid)
{
    const uint32_t base = sb + slot * STG;
    const int q = tid & 3;
    // A tiles: t = 0..3 (t>>1 selects hi/lo)
#pragma unroll
    for (int t = 0; t < 4; ++t) {
        const int row = (t * 64 + (tid >> 2)) & 127;
        const uint32_t dst = base + (t >> 1) * ATSZ + sw64((uint32_t)row * 64u + q * 16u);
        const uint4* src = ((t >> 1) ? Al4 : Ah4)
                         + (size_t)(m0 + row) * (DD / 8) + c * 4 + q;
        CP_ASYNC16(dst, src);
    }
    // B tiles: t = 0 (hi), 1 (lo)
#pragma unroll
    for (int t = 0; t < 2; ++t) {
        const int row = tid >> 2;   // 0..63
        const uint32_t dst = base + 2 * ATSZ + t * BTSZ
                           + sw64((uint32_t)row * 64u + q * 16u);
        const uint4* src = (t ? Bl4 : Bh4)
                         + (size_t)(n0 + row) * (DD / 8) + c * 4 + q;
        CP_ASYNC16(dst, src);
    }
}

__device__ __forceinline__ void gemm_core(
    const uint4* __restrict__ Ah4, const uint4* __restrict__ Al4,
    const uint4* __restrict__ Bh4, const uint4* __restrict__ Bl4,
    const float* __restrict__ bias, float* __restrict__ C)
{
    extern __shared__ char smem[];
    const uint32_t sb = s2u(smem);
    const int tid  = threadIdx.x;
    const int wid  = tid >> 5;
    const int lane = tid & 31;
    const int n0 = blockIdx.x * 64, m0 = blockIdx.y * 128;

    const int wm = wid >> 1;            // 0..3
    const int wn = wid & 1;             // 0..1

    const int r  = lane & 7;
    const int md = lane >> 3;
    const int rowA = wm * 32 + (md & 1) * 8 + r;
    const uint32_t bA = (md >> 1) * 16;
    const int rowB = wn * 32 + (md >> 1) * 8 + r;
    const uint32_t bB = (md & 1) * 16;

    float acc[2][4][4];
#pragma unroll
    for (int f = 0; f < 2; ++f)
#pragma unroll
        for (int j = 0; j < 4; ++j)
#pragma unroll
            for (int e = 0; e < 4; ++e) acc[f][j][e] = 0.f;

    load_stage(Ah4, Al4, Bh4, Bl4, sb, 0, 0, m0, n0, tid); CP_COMMIT();
    load_stage(Ah4, Al4, Bh4, Bl4, sb, 1, 1, m0, n0, tid); CP_COMMIT();
    load_stage(Ah4, Al4, Bh4, Bl4, sb, 2, 2, m0, n0, tid); CP_COMMIT();

#pragma unroll 1
    for (int c = 0; c < NC; ++c) {
        const int rem = NC - 1 - c;
        if (rem >= 2) CP_WAIT2(); else if (rem == 1) CP_WAIT1(); else CP_WAIT0();
        __syncthreads();

        const uint32_t base = sb + (c & 3) * STG;
        const uint32_t stAh = base;
        const uint32_t stAl = base + ATSZ;
        const uint32_t stBh = base + 2 * ATSZ;
        const uint32_t stBl = base + 2 * ATSZ + BTSZ;

#pragma unroll
        for (int ks = 0; ks < 2; ++ks) {
            const uint32_t kb = ks * 32;
            uint32_t ah[2][4], al[2][4];
#pragma unroll
            for (int f = 0; f < 2; ++f) {
                const uint32_t off = sw64((uint32_t)(rowA + f * 16) * 64u + kb + bA);
                ldsm_x4(ah[f][0], ah[f][1], ah[f][2], ah[f][3], stAh + off);
                ldsm_x4(al[f][0], al[f][1], al[f][2], al[f][3], stAl + off);
            }
            uint32_t bh[4][2], bl[4][2];
#pragma unroll
            for (int p = 0; p < 2; ++p) {
                const uint32_t off = sw64((uint32_t)(rowB + p * 16) * 64u + kb + bB);
                ldsm_x4(bh[2*p][0], bh[2*p][1], bh[2*p+1][0], bh[2*p+1][1], stBh + off);
                ldsm_x4(bl[2*p][0], bl[2*p][1], bl[2*p+1][0], bl[2*p+1][1], stBl + off);
            }
#pragma unroll
            for (int f = 0; f < 2; ++f)
#pragma unroll
                for (int j = 0; j < 4; ++j) {
                    mma16816(acc[f][j], ah[f], bh[j]);
                    mma16816(acc[f][j], ah[f], bl[j]);
                    mma16816(acc[f][j], al[f], bh[j]);
                }
        }
        if (c + 3 < NC) {
            load_stage(Ah4, Al4, Bh4, Bl4, sb, (c + 3) & 3, c + 3, m0, n0, tid);
            CP_COMMIT();
        }
    }

    // epilogue
#pragma unroll
    for (int f = 0; f < 2; ++f) {
        const int grow = m0 + wm * 32 + f * 16 + (lane >> 2);
        float* c0 = C + (size_t)grow * DD;
        float* c1 = c0 + 8 * DD;
#pragma unroll
        for (int j = 0; j < 4; ++j) {
            const int col = n0 + wn * 32 + j * 8 + (lane & 3) * 2;
            const float2 bb = *(const float2*)(bias + col);
            *(float2*)(c0 + col) = make_float2(acc[f][j][0] + bb.x, acc[f][j][1] + bb.y);
            *(float2*)(c1 + col) = make_float2(acc[f][j][2] + bb.x, acc[f][j][3] + bb.y);
        }
    }
}

__global__ void __launch_bounds__(256, 2)
k_gemm_gv(const float* __restrict__ bg, const float* __restrict__ bv)
{
    if (blockIdx.z == 0)
        gemm_core((const uint4*)xh_buf, (const uint4*)xl_buf,
                  (const uint4*)wgh_buf, (const uint4*)wgl_buf, bg, g_buf);
    else
        gemm_core((const uint4*)xh_buf, (const uint4*)xl_buf,
                  (const uint4*)wvh_buf, (const uint4*)wvl_buf, bv, v_buf);
}

__global__ void __launch_bounds__(256, 2)
k_gemm_o(const float* __restrict__ bo, float* __restrict__ out)
{
    gemm_core((const uint4*)oh_buf, (const uint4*)ol_buf,
              (const uint4*)woh_buf, (const uint4*)wol_buf, bo, out);
}

// ---------------- per-(h,t) L2 norms of g + zero suminv --------------------
__global__ void __launch_bounds__(256)
k_norm()
{
    if (blockIdx.x == 0 && threadIdx.x < NH) suminv_buf[threadIdx.x] = 0.f;
    const int r    = blockIdx.x * 8 + (threadIdx.x >> 5);
    const int lane = threadIdx.x & 31;
    const int h    = r >> 11;
    const int t    = r & (TT - 1);
    const float2 v = *(const float2*)(g_buf + (size_t)t * DD + h * HDIM + 2 * lane);
    float s = v.x * v.x + v.y * v.y;
#pragma unroll
    for (int o = 16; o > 0; o >>= 1) s += __shfl_xor_sync(0xffffffffu, s, o);
    if (lane == 0) norm_buf[r] = sqrtf(s);
}

// ---------------- windowed scores + gene_means denom (8 rows / block) ------
__global__ void __launch_bounds__(256)
k_scores()
{
    const int i0 = blockIdx.x * 8;
    const int h  = blockIdx.y;
    const int tid = threadIdx.x;

    const int jstart0 = (i0 > WIN) ? (i0 - WIN) : 0;
    const int span    = (i0 + 7) - jstart0 + 1;

    __shared__ __align__(16) float4 gwT[16][JT];
    __shared__ float nw[JT];
    __shared__ float rowsum[8];

    const float4* g4 = (const float4*)g_buf;
    for (int idx = tid; idx < span * 16; idx += 256) {
        int jj = idx >> 4;
        int q  = idx & 15;
        gwT[q][jj] = g4[(size_t)(jstart0 + jj) * (DD / 4) + h * (HDIM / 4) + q];
    }
    for (int idx = tid; idx < span; idx += 256)
        nw[idx] = norm_buf[h * TT + jstart0 + idx];
    if (tid < 8) rowsum[tid] = 0.f;
    __syncthreads();

    const int group = tid >> 7;
    const int jl    = tid & 127;
    const int ibase = i0 + group * 4;
    const int wi0   = ibase - jstart0;

    float psum[4] = {0.f, 0.f, 0.f, 0.f};

    for (int jj = jl; jj < span; jj += 128) {
        float dot[4] = {0.f, 0.f, 0.f, 0.f};
#pragma unroll
        for (int q = 0; q < 16; ++q) {
            float4 b = gwT[q][jj];
#pragma unroll
            for (int r = 0; r < 4; ++r) {
                float4 a = gwT[q][wi0 + r];
                dot[r] = fmaf(a.x, b.x, dot[r]);
                dot[r] = fmaf(a.y, b.y, dot[r]);
                dot[r] = fmaf(a.z, b.z, dot[r]);
                dot[r] = fmaf(a.w, b.w, dot[r]);
            }
        }
        float njj = nw[jj];
#pragma unroll
        for (int r = 0; r < 4; ++r) {
            const int i   = ibase + r;
            const int wi  = wi0 + r;
            const int off = ((i > WIN) ? (i - WIN) : 0) - jstart0;
            if (jj >= off && jj <= wi) {
                float c = dot[r] / (nw[wi] * njj + 1e-8f);
                if (c != c) c = 0.f;
                float p = (c + 1.f) * 0.5f;
                p_buf[(size_t)(h * TT + i) * PSTR + (jj - off)] = p;
                psum[r] += p;
            }
        }
    }

#pragma unroll
    for (int r = 0; r < 4; ++r) {
        float s = psum[r];
#pragma unroll
        for (int o = 16; o > 0; o >>= 1) s += __shfl_xor_sync(0xffffffffu, s, o);
        if ((tid & 31) == 0) atomicAdd(&rowsum[group * 4 + r], s);
    }
    __syncthreads();

    if (tid < 8) {
        const int i   = i0 + tid;
        const int cnt = i - ((i > WIN) ? (i - WIN) : 0) + 1;
        float gm = (rowsum[tid] + 0.5f * (float)(TT - cnt)) * (1.f / (float)TT);
        float dn = gm + 0.5f;
        denom_buf[h * TT + i] = dn;
        atomicAdd(&suminv_buf[h], 1.f / dn);
    }
}

// ---------------- softmax + attn@v (16 rows / block), emits bf16 hi/lo -----
#define SATT_STRIDE 20
#define ATTN_SMEM   (JTA * HDIM * 4 + JTA * SATT_STRIDE * 4 + 4 * IT * HDIM * 4 + 64)

__global__ void __launch_bounds__(256)
k_attnv()
{
    extern __shared__ char dynsm[];
    float (*vw)[HDIM]       = (float(*)[HDIM])dynsm;                        // [JTA][64]
    float (*sattn)[SATT_STRIDE] =
        (float(*)[SATT_STRIDE])(dynsm + JTA * HDIM * 4);                    // [JTA][20]
    float (*red)[IT][HDIM]  =
        (float(*)[IT][HDIM])(dynsm + JTA * HDIM * 4 + JTA * SATT_STRIDE * 4); // [4][16][64]
    float* invs = (float*)(dynsm + JTA * HDIM * 4 + JTA * SATT_STRIDE * 4
                           + 4 * IT * HDIM * 4);                            // [16]

    const int i0  = blockIdx.x * IT;
    const int h   = blockIdx.y;
    const int tid = threadIdx.x;
    const int wid = tid >> 5;
    const int lane = tid & 31;

    const int jstart0 = (i0 > WIN) ? (i0 - WIN) : 0;
    const int span    = (i0 + IT - 1) - jstart0 + 1;        // <= 144

    const float4* v4 = (const float4*)v_buf;
    for (int idx = tid; idx < span * 16; idx += 256) {
        int jj = idx >> 4;
        int q  = idx & 15;
        ((float4*)&vw[jj][0])[q] = v4[(size_t)(jstart0 + jj) * (DD / 4) + h * (HDIM / 4) + q];
    }
    __syncthreads();

    // phase A: warp wid handles rows wid and wid+8
#pragma unroll
    for (int rr = 0; rr < 2; ++rr) {
        const int w = wid + rr * 8;
        const int i = i0 + w;
        const size_t row = (size_t)h * TT + i;
        const float fit  = 1.f / (denom_buf[row] * suminv_buf[h]);
        const int off = ((i > WIN) ? (i - WIN) : 0) - jstart0;
        const int wi  = i - jstart0;

        float m = -1e30f;
        for (int q = lane; q < JTA; q += 32) {
            bool in = (q >= off) && (q <= wi);
            float s = in ? fit * p_buf[row * PSTR + (q - off)] : -1e30f;
            sattn[q][w] = s;
            m = fmaxf(m, s);
        }
#pragma unroll
        for (int o = 16; o > 0; o >>= 1) m = fmaxf(m, __shfl_xor_sync(0xffffffffu, m, o));

        float ss = 0.f;
        for (int q = lane; q < JTA; q += 32) {
            float e = expf(sattn[q][w] - m);
            sattn[q][w] = e;
            ss += e;
        }
#pragma unroll
        for (int o = 16; o > 0; o >>= 1) ss += __shfl_xor_sync(0xffffffffu, ss, o);
        if (lane == 0) invs[w] = 1.f / ss;
    }
    __syncthreads();

    // phase B
    {
        const int d  = tid & 63;
        const int qq = tid >> 6;
        float acc[IT];
#pragma unroll
        for (int w = 0; w < IT; ++w) acc[w] = 0.f;

        for (int jj = qq; jj < span; jj += 4) {
            const float vv = vw[jj][d];
            const float4 s0 = *(const float4*)&sattn[jj][0];
            const float4 s1 = *(const float4*)&sattn[jj][4];
            const float4 s2 = *(const float4*)&sattn[jj][8];
            const float4 s3 = *(const float4*)&sattn[jj][12];
            acc[0]  = fmaf(s0.x, vv, acc[0]);  acc[1]  = fmaf(s0.y, vv, acc[1]);
            acc[2]  = fmaf(s0.z, vv, acc[2]);  acc[3]  = fmaf(s0.w, vv, acc[3]);
            acc[4]  = fmaf(s1.x, vv, acc[4]);  acc[5]  = fmaf(s1.y, vv, acc[5]);
            acc[6]  = fmaf(s1.z, vv, acc[6]);  acc[7]  = fmaf(s1.w, vv, acc[7]);
            acc[8]  = fmaf(s2.x, vv, acc[8]);  acc[9]  = fmaf(s2.y, vv, acc[9]);
            acc[10] = fmaf(s2.z, vv, acc[10]); acc[11] = fmaf(s2.w, vv, acc[11]);
            acc[12] = fmaf(s3.x, vv, acc[12]); acc[13] = fmaf(s3.y, vv, acc[13]);
            acc[14] = fmaf(s3.z, vv, acc[14]); acc[15] = fmaf(s3.w, vv, acc[15]);
        }
#pragma unroll
        for (int w = 0; w < IT; ++w) red[qq][w][d] = acc[w];
        __syncthreads();

        if (qq == 0) {
#pragma unroll
            for (int w = 0; w < IT; ++w) {
                float s = (red[0][w][d] + red[1][w][d]) + (red[2][w][d] + red[3][w][d]);
                float val = s * invs[w];
                const size_t idx = (size_t)(i0 + w) * DD + h * HDIM + d;
                __nv_bfloat16 hv = __float2bfloat16(val);
                __nv_bfloat16 lv = __float2bfloat16(val - __bfloat162float(hv));
                oh_buf[idx] = hv;
                ol_buf[idx] = lv;
            }
        }
    }
}

// ---------------- launch ---------------------------------------------------
extern "C" void kernel_launch(void* const* d_in, const int* in_sizes, int n_in,
                              void* d_out, int out_size)
{
    const float* x  = (const float*)d_in[0];
    const float* Wg = (const float*)d_in[1];
    const float* bg = (const float*)d_in[2];
    const float* Wv = (const float*)d_in[3];
    const float* bv = (const float*)d_in[4];
    const float* Wo = (const float*)d_in[5];
    const float* bo = (const float*)d_in[6];
    float* out = (float*)d_out;

    cudaFuncSetAttribute(k_gemm_gv, cudaFuncAttributeMaxDynamicSharedMemorySize, SMEM_G);
    cudaFuncSetAttribute(k_gemm_o,  cudaFuncAttributeMaxDynamicSharedMemorySize, SMEM_G);
    cudaFuncSetAttribute(k_attnv,   cudaFuncAttributeMaxDynamicSharedMemorySize, ATTN_SMEM);

    k_conv<<<(TT * DD) / 1024, 256>>>(x,  0);
    k_conv<<<(DD * DD) / 1024, 256>>>(Wg, 1);
    k_conv<<<(DD * DD) / 1024, 256>>>(Wv, 2);
    k_conv<<<(DD * DD) / 1024, 256>>>(Wo, 3);

    dim3 gemm_gv(DD / 64, TT / 128, 2);
    k_gemm_gv<<<gemm_gv, 256, SMEM_G>>>(bg, bv);

    k_norm<<<(NH * TT) / 8, 256>>>();

    dim3 sc_grid(TT / 8, NH);
    k_scores<<<sc_grid, 256>>>();

    dim3 av_grid(TT / IT, NH);
    k_attnv<<<av_grid, 256, ATTN_SMEM>>>();

    dim3 gemm_o(DD / 64, TT / 128, 1);
    k_gemm_o<<<gemm_o, 256, SMEM_G>>>(bo, out);
}